// round 1
// baseline (speedup 1.0000x reference)
#include <cuda_runtime.h>

#define B_SZ 4096
#define T_SZ 2048
#define H_SZ 32

__device__ int g_seq_counter;

__global__ void reset_counter_kernel() { g_seq_counter = 0; }

typedef unsigned long long u64;

__device__ __forceinline__ float fast_ex2(float x) {
    float r; asm("ex2.approx.f32 %0, %1;" : "=f"(r) : "f"(x)); return r;
}
__device__ __forceinline__ float fast_rcp(float x) {
    float r; asm("rcp.approx.f32 %0, %1;" : "=f"(r) : "f"(x)); return r;
}
// sigmoid(x) = 1 / (1 + 2^(-x*log2(e)))
__device__ __forceinline__ float sigmoid_(float x) {
    return fast_rcp(1.0f + fast_ex2(-1.44269504f * x));
}
// tanh(x) = 2/(1 + 2^(-2x*log2(e))) - 1
__device__ __forceinline__ float tanh_(float x) {
    return fmaf(2.0f, fast_rcp(1.0f + fast_ex2(-2.88539008f * x)), -1.0f);
}

// Packed dual-fp32 FMA (sm_100+): ptxas only emits FFMA2 via explicit PTX.
__device__ __forceinline__ u64 ffma2(u64 a, u64 b, u64 c) {
    u64 d; asm("fma.rn.f32x2 %0, %1, %2, %3;" : "=l"(d) : "l"(a), "l"(b), "l"(c));
    return d;
}
__device__ __forceinline__ u64 pack2(float lo, float hi) {
    u64 r; asm("mov.b64 %0, {%1, %2};" : "=l"(r) : "f"(lo), "f"(hi)); return r;
}
__device__ __forceinline__ void unpack2(u64 v, float& lo, float& hi) {
    asm("mov.b64 {%0, %1}, %2;" : "=f"(lo), "=f"(hi) : "l"(v));
}

__global__ __launch_bounds__(128)
void bilstm_kernel(const float* __restrict__ x,
                   const int* __restrict__ lengths,
                   const float* __restrict__ w_ih,
                   const float* __restrict__ w_hh,
                   const float* __restrict__ b_ih,
                   const float* __restrict__ b_hh,
                   const float* __restrict__ fc_w,
                   const float* __restrict__ fc_b,
                   const float* __restrict__ fc2_w,
                   const float* __restrict__ fc2_b,
                   float* __restrict__ out)
{
    const int lane = threadIdx.x & 31;
    const int wrp  = threadIdx.x >> 5;

    // Per-warp h broadcast buffers (double-buffered so one __syncwarp per step suffices)
    __shared__ __align__(16) float hsh[2][4][32];

    // ---- Load recurrent weights into registers ONCE; reused for every sequence ----
    // Lane j owns hidden unit j => gate rows j, 32+j, 64+j, 96+j (i, f, g, o).
    u64   whh[4][16];   // packed pairs over k
    float wih[4], bs[4];
#pragma unroll
    for (int g = 0; g < 4; ++g) {
        const int row = g * 32 + lane;
        wih[g] = __ldg(w_ih + row);                       // (4H,1)
        bs[g]  = __ldg(b_ih + row) + __ldg(b_hh + row);   // fused bias
#pragma unroll
        for (int p = 0; p < 16; ++p)
            whh[g][p] = *reinterpret_cast<const u64*>(w_hh + row * 32 + 2 * p);
    }

    const unsigned FULL = 0xffffffffu;

    for (;;) {
        // ---- dynamic work queue: grab next sequence ----
        int s = 0;
        if (lane == 0) s = atomicAdd(&g_seq_counter, 1);
        s = __shfl_sync(FULL, s, 0);
        if (s >= B_SZ) break;

        const float* xb = x + (size_t)s * T_SZ;
        const int len = __ldg(lengths + s);   // in [1, T]

        float h = 0.0f, c = 0.0f;
        int t = len - 1;
        float xt = __ldg(xb + t);             // prefetched current x
        int buf = 0;

        for (; t >= 0; --t) {
            // prefetch next step's x (uniform, predicated off at t==0)
            float xn = (t > 0) ? __ldg(xb + t - 1) : 0.0f;

            // broadcast h across the warp via shared memory
            hsh[buf][wrp][lane] = h;
            __syncwarp();

            // gates = bias + x*w_ih + W_hh @ h  (packed 2-wide over k)
            u64 acc0 = pack2(fmaf(xt, wih[0], bs[0]), 0.0f);
            u64 acc1 = pack2(fmaf(xt, wih[1], bs[1]), 0.0f);
            u64 acc2 = pack2(fmaf(xt, wih[2], bs[2]), 0.0f);
            u64 acc3 = pack2(fmaf(xt, wih[3], bs[3]), 0.0f);

            const u64* hp = reinterpret_cast<const u64*>(&hsh[buf][wrp][0]);
#pragma unroll
            for (int p = 0; p < 16; ++p) {
                const u64 hv = hp[p];          // LDS.64 broadcast (conflict-free)
                acc0 = ffma2(hv, whh[0][p], acc0);
                acc1 = ffma2(hv, whh[1][p], acc1);
                acc2 = ffma2(hv, whh[2][p], acc2);
                acc3 = ffma2(hv, whh[3][p], acc3);
            }

            float a, b2;
            unpack2(acc0, a, b2); const float gi = a + b2;
            unpack2(acc1, a, b2); const float gf = a + b2;
            unpack2(acc2, a, b2); const float gg = a + b2;
            unpack2(acc3, a, b2); const float go = a + b2;

            const float iv = sigmoid_(gi);
            const float fv = sigmoid_(gf);
            const float gv = tanh_(gg);
            const float ov = sigmoid_(go);

            c = fmaf(fv, c, iv * gv);
            h = ov * tanh_(c);

            xt = xn;
            buf ^= 1;
        }

        // ---- FC head: elu(h @ fc_w.T + fc_b) @ fc2_w.T + fc2_b -> sigmoid ----
        __syncwarp();                 // all lanes done reading LSTM buffers
        hsh[0][wrp][lane] = h;
        __syncwarp();

        float o1 = __ldg(fc_b + lane);
        float o2 = __ldg(fc_b + lane + 32);
#pragma unroll
        for (int k = 0; k < 32; ++k) {
            const float hk = hsh[0][wrp][k];
            o1 = fmaf(hk, __ldg(fc_w + lane * 32 + k), o1);
            o2 = fmaf(hk, __ldg(fc_w + (lane + 32) * 32 + k), o2);
        }
        // ELU (alpha = 1)
        o1 = (o1 > 0.0f) ? o1 : (fast_ex2(1.44269504f * o1) - 1.0f);
        o2 = (o2 > 0.0f) ? o2 : (fast_ex2(1.44269504f * o2) - 1.0f);

        float part = o1 * __ldg(fc2_w + lane) + o2 * __ldg(fc2_w + lane + 32);
#pragma unroll
        for (int d = 16; d >= 1; d >>= 1)
            part += __shfl_xor_sync(FULL, part, d);

        if (lane == 0)
            out[s] = sigmoid_(part + __ldg(fc2_b));

        __syncwarp();                 // protect hsh[0] before next sequence
    }
}

extern "C" void kernel_launch(void* const* d_in, const int* in_sizes, int n_in,
                              void* d_out, int out_size)
{
    const float* x       = (const float*)d_in[0];
    const int*   lengths = (const int*)  d_in[1];
    const float* w_ih    = (const float*)d_in[2];
    const float* w_hh    = (const float*)d_in[3];
    const float* b_ih    = (const float*)d_in[4];
    const float* b_hh    = (const float*)d_in[5];
    const float* fc_w    = (const float*)d_in[6];
    const float* fc_b    = (const float*)d_in[7];
    const float* fc2_w   = (const float*)d_in[8];
    const float* fc2_b   = (const float*)d_in[9];
    float* out = (float*)d_out;

    reset_counter_kernel<<<1, 1>>>();
    // Persistent-ish launch: enough blocks to fill the chip at ~3 blocks/SM
    // (register-limited); the atomic queue balances the skewed sequence lengths.
    bilstm_kernel<<<592, 128>>>(x, lengths, w_ih, w_hh, b_ih, b_hh,
                                fc_w, fc_b, fc2_w, fc2_b, out);
}

// round 3
// speedup vs baseline: 1.2899x; 1.2899x over previous
#include <cuda_runtime.h>

#define B_SZ 4096
#define T_SZ 2048
#define H_SZ 32

typedef unsigned long long u64;

__device__ int g_counter;
__device__ int g_hist[2048];
__device__ int g_order[B_SZ];

// ---------------- scheduling prologue: counting sort by descending length ---------
__global__ void init_kernel() {
    int i = blockIdx.x * blockDim.x + threadIdx.x;
    if (i < 2048) g_hist[i] = 0;
    if (i == 0) g_counter = 0;
}
__global__ void hist_kernel(const int* __restrict__ lengths) {
    int i = blockIdx.x * blockDim.x + threadIdx.x;
    if (i < B_SZ) atomicAdd(&g_hist[T_SZ - lengths[i]], 1);
}
__global__ void scan_kernel() {
    __shared__ int s[2048];
    int tid = threadIdx.x;
    int o0 = g_hist[tid], o1 = g_hist[tid + 1024];
    s[tid] = o0; s[tid + 1024] = o1;
    __syncthreads();
    for (int off = 1; off < 2048; off <<= 1) {
        int v0 = s[tid]        + ((tid        >= off) ? s[tid - off]        : 0);
        int v1 = s[tid + 1024] + ((tid + 1024 >= off) ? s[tid + 1024 - off] : 0);
        __syncthreads();
        s[tid] = v0; s[tid + 1024] = v1;
        __syncthreads();
    }
    g_hist[tid]        = s[tid]        - o0;   // exclusive prefix = start offset
    g_hist[tid + 1024] = s[tid + 1024] - o1;
}
__global__ void scatter_kernel(const int* __restrict__ lengths) {
    int i = blockIdx.x * blockDim.x + threadIdx.x;
    if (i < B_SZ) {
        int pos = atomicAdd(&g_hist[T_SZ - lengths[i]], 1);
        g_order[pos] = i;
    }
}

// ---------------- math helpers ---------------------------------------------------
__device__ __forceinline__ float fast_ex2(float x) {
    float r; asm("ex2.approx.f32 %0, %1;" : "=f"(r) : "f"(x)); return r;
}
__device__ __forceinline__ float fast_rcp(float x) {
    float r; asm("rcp.approx.f32 %0, %1;" : "=f"(r) : "f"(x)); return r;
}
__device__ __forceinline__ float sigmoid_(float x) {       // plain sigmoid (head only)
    return fast_rcp(1.0f + fast_ex2(-1.44269504f * x));
}
__device__ __forceinline__ u64 ffma2(u64 a, u64 b, u64 c) {
    u64 d; asm("fma.rn.f32x2 %0, %1, %2, %3;" : "=l"(d) : "l"(a), "l"(b), "l"(c));
    return d;
}
__device__ __forceinline__ u64 mul2(u64 a, u64 b) {
    u64 d; asm("mul.rn.f32x2 %0, %1, %2;" : "=l"(d) : "l"(a), "l"(b));
    return d;
}
__device__ __forceinline__ u64 pack2(float lo, float hi) {
    u64 r; asm("mov.b64 %0, {%1, %2};" : "=l"(r) : "f"(lo), "f"(hi)); return r;
}
__device__ __forceinline__ void unpack2(u64 v, float& lo, float& hi) {
    asm("mov.b64 {%0, %1}, %2;" : "=f"(lo), "=f"(hi) : "l"(v));
}

// ---------------- main persistent kernel -----------------------------------------
__global__ __launch_bounds__(128, 3)
void bilstm_kernel(const float* __restrict__ x,
                   const int* __restrict__ lengths,
                   const float* __restrict__ w_ih,
                   const float* __restrict__ w_hh,
                   const float* __restrict__ b_ih,
                   const float* __restrict__ b_hh,
                   const float* __restrict__ fc_w,
                   const float* __restrict__ fc_b,
                   const float* __restrict__ fc2_w,
                   const float* __restrict__ fc2_b,
                   float* __restrict__ out)
{
    const int lane = threadIdx.x & 31;
    const int wrp  = threadIdx.x >> 5;

    __shared__ __align__(16) float hsh[2][4][32];   // per-warp h broadcast (dbl buf)
    __shared__ __align__(16) float xs[4][2][32];    // per-warp x chunk ring (dbl buf)

    // Scale sigmoid/tanh arguments directly into the weights:
    //   sigmoid(v) = rcp(1 + ex2(-1.4427 v)),  tanh(v) = 2 rcp(1 + ex2(-2.8854 v)) - 1
    const float gsc[4] = {-1.44269504f, -1.44269504f, -2.88539008f, -1.44269504f};

    u64   whh[4][16];
    float wihs[4], bss[4];
#pragma unroll
    for (int g = 0; g < 4; ++g) {
        const int row = g * 32 + lane;
        const float sc = gsc[g];
        wihs[g] = sc * __ldg(w_ih + row);
        bss[g]  = sc * (__ldg(b_ih + row) + __ldg(b_hh + row));
#pragma unroll
        for (int p = 0; p < 16; ++p) {
            float2 wv = *reinterpret_cast<const float2*>(w_hh + row * 32 + 2 * p);
            whh[g][p] = pack2(sc * wv.x, sc * wv.y);
        }
    }

    const unsigned FULL = 0xffffffffu;

    for (;;) {
        int s0 = 0;
        if (lane == 0) s0 = atomicAdd(&g_counter, 1);
        s0 = __shfl_sync(FULL, s0, 0);
        if (s0 >= B_SZ) break;

        const int idx = g_order[s0];
        const int len = __ldg(lengths + idx);
        const float* xb = x + (size_t)idx * T_SZ;

        int t = len - 1;
        const int ctop = t >> 5;
        float pend;                                  // in-flight next chunk (per lane)
        if ((t & 31) == 31) {
            // first loop iteration's boundary code will store this chunk
            pend = __ldg(xb + (ctop << 5) + lane);
        } else {
            xs[wrp][ctop & 1][lane] = __ldg(xb + (ctop << 5) + lane);
            pend = (ctop > 0) ? __ldg(xb + ((ctop - 1) << 5) + lane) : 0.0f;
        }

        float h = 0.0f, cc = 0.0f;
        int buf = 0;

        for (; t >= 0; --t) {
            if ((t & 31) == 31) {                    // entering chunk t>>5
                xs[wrp][(t >> 5) & 1][lane] = pend;  // arrived >=32 steps ago
                const int nc = (t >> 5) - 1;
                pend = (nc >= 0) ? __ldg(xb + (nc << 5) + lane) : 0.0f;
            }

            hsh[buf][wrp][lane] = h;
            __syncwarp();

            const float xt = xs[wrp][(t >> 5) & 1][t & 31];

            // off-chain scaled bias + input terms
            const float bx0 = fmaf(xt, wihs[0], bss[0]);
            const float bx1 = fmaf(xt, wihs[1], bss[1]);
            const float bx2 = fmaf(xt, wihs[2], bss[2]);
            const float bx3 = fmaf(xt, wihs[3], bss[3]);

            const ulonglong2* hp =
                reinterpret_cast<const ulonglong2*>(&hsh[buf][wrp][0]);

            ulonglong2 hv = hp[0];                   // LDS.128 broadcast
            u64 a0 = mul2(hv.x, whh[0][0]);
            u64 a1 = mul2(hv.x, whh[1][0]);
            u64 a2 = mul2(hv.x, whh[2][0]);
            u64 a3 = mul2(hv.x, whh[3][0]);
            a0 = ffma2(hv.y, whh[0][1], a0);
            a1 = ffma2(hv.y, whh[1][1], a1);
            a2 = ffma2(hv.y, whh[2][1], a2);
            a3 = ffma2(hv.y, whh[3][1], a3);
#pragma unroll
            for (int q = 1; q < 8; ++q) {
                hv = hp[q];
                a0 = ffma2(hv.x, whh[0][2 * q], a0);
                a1 = ffma2(hv.x, whh[1][2 * q], a1);
                a2 = ffma2(hv.x, whh[2][2 * q], a2);
                a3 = ffma2(hv.x, whh[3][2 * q], a3);
                a0 = ffma2(hv.y, whh[0][2 * q + 1], a0);
                a1 = ffma2(hv.y, whh[1][2 * q + 1], a1);
                a2 = ffma2(hv.y, whh[2][2 * q + 1], a2);
                a3 = ffma2(hv.y, whh[3][2 * q + 1], a3);
            }

            float lo, hi;
            unpack2(a0, lo, hi); const float gi = (lo + hi) + bx0;  // pre-scaled
            unpack2(a1, lo, hi); const float gf = (lo + hi) + bx1;
            unpack2(a2, lo, hi); const float gg = (lo + hi) + bx2;
            unpack2(a3, lo, hi); const float go = (lo + hi) + bx3;

            const float iv = fast_rcp(1.0f + fast_ex2(gi));
            const float fv = fast_rcp(1.0f + fast_ex2(gf));
            const float gv = fmaf(2.0f, fast_rcp(1.0f + fast_ex2(gg)), -1.0f);
            const float ov = fast_rcp(1.0f + fast_ex2(go));

            cc = fmaf(fv, cc, iv * gv);
            const float tv = fmaf(2.0f,
                fast_rcp(1.0f + fast_ex2(-2.88539008f * cc)), -1.0f);
            h = ov * tv;

            buf ^= 1;
        }

        // ---- FC head: sigmoid(fc2(elu(fc1(h)))) ----
        __syncwarp();
        hsh[0][wrp][lane] = h;
        __syncwarp();

        float o1 = __ldg(fc_b + lane);
        float o2 = __ldg(fc_b + lane + 32);
#pragma unroll
        for (int k = 0; k < 32; ++k) {
            const float hk = hsh[0][wrp][k];
            o1 = fmaf(hk, __ldg(fc_w + lane * 32 + k), o1);
            o2 = fmaf(hk, __ldg(fc_w + (lane + 32) * 32 + k), o2);
        }
        o1 = (o1 > 0.0f) ? o1 : (fast_ex2(1.44269504f * o1) - 1.0f);  // ELU
        o2 = (o2 > 0.0f) ? o2 : (fast_ex2(1.44269504f * o2) - 1.0f);

        float part = o1 * __ldg(fc2_w + lane) + o2 * __ldg(fc2_w + lane + 32);
#pragma unroll
        for (int d = 16; d >= 1; d >>= 1)
            part += __shfl_xor_sync(FULL, part, d);

        if (lane == 0)
            out[idx] = sigmoid_(part + __ldg(fc2_b));

        __syncwarp();
    }
}

extern "C" void kernel_launch(void* const* d_in, const int* in_sizes, int n_in,
                              void* d_out, int out_size)
{
    const float* x       = (const float*)d_in[0];
    const int*   lengths = (const int*)  d_in[1];
    const float* w_ih    = (const float*)d_in[2];
    const float* w_hh    = (const float*)d_in[3];
    const float* b_ih    = (const float*)d_in[4];
    const float* b_hh    = (const float*)d_in[5];
    const float* fc_w    = (const float*)d_in[6];
    const float* fc_b    = (const float*)d_in[7];
    const float* fc2_w   = (const float*)d_in[8];
    const float* fc2_b   = (const float*)d_in[9];
    float* out = (float*)d_out;

    init_kernel<<<2, 1024>>>();
    hist_kernel<<<4, 1024>>>(lengths);
    scan_kernel<<<1, 1024>>>();
    scatter_kernel<<<4, 1024>>>(lengths);

    // 148 SMs x 3 resident blocks; atomic queue + longest-first order balances.
    bilstm_kernel<<<444, 128>>>(x, lengths, w_ih, w_hh, b_ih, b_hh,
                                fc_w, fc_b, fc2_w, fc2_b, out);
}

// round 5
// speedup vs baseline: 1.3657x; 1.0588x over previous
#include <cuda_runtime.h>

#define B_SZ 4096
#define T_SZ 2048

typedef unsigned long long u64;

__device__ int g_counter;
__device__ int g_order[B_SZ];

// ---------------- fused scheduling prologue: counting sort (descending length) ----
__global__ __launch_bounds__(1024)
void sort_kernel(const int* __restrict__ lengths)
{
    __shared__ int hist[2048];
    const int tid = threadIdx.x;

    hist[tid] = 0; hist[tid + 1024] = 0;
    __syncthreads();

    for (int i = tid; i < B_SZ; i += 1024)
        atomicAdd(&hist[T_SZ - lengths[i]], 1);
    __syncthreads();

    const int o0 = hist[tid], o1 = hist[tid + 1024];
    // Hillis-Steele inclusive scan over 2048 bins
    for (int off = 1; off < 2048; off <<= 1) {
        int v0 = hist[tid]        + ((tid        >= off) ? hist[tid - off]        : 0);
        int v1 = hist[tid + 1024] + ((tid + 1024 >= off) ? hist[tid + 1024 - off] : 0);
        __syncthreads();
        hist[tid] = v0; hist[tid + 1024] = v1;
        __syncthreads();
    }
    hist[tid]        -= o0;          // exclusive prefix = start offsets
    hist[tid + 1024] -= o1;
    __syncthreads();

    for (int i = tid; i < B_SZ; i += 1024) {
        int pos = atomicAdd(&hist[T_SZ - lengths[i]], 1);
        g_order[pos] = i;
    }
    if (tid == 0) g_counter = 0;
}

// ---------------- math helpers ---------------------------------------------------
__device__ __forceinline__ float fast_ex2(float x) {
    float r; asm("ex2.approx.f32 %0, %1;" : "=f"(r) : "f"(x)); return r;
}
__device__ __forceinline__ float fast_rcp(float x) {
    float r; asm("rcp.approx.f32 %0, %1;" : "=f"(r) : "f"(x)); return r;
}
__device__ __forceinline__ float sigmoid_(float x) {          // head only
    return fast_rcp(1.0f + fast_ex2(-1.44269504f * x));
}
__device__ __forceinline__ u64 ffma2(u64 a, u64 b, u64 c) {
    u64 d; asm("fma.rn.f32x2 %0, %1, %2, %3;" : "=l"(d) : "l"(a), "l"(b), "l"(c));
    return d;
}
__device__ __forceinline__ u64 mul2(u64 a, u64 b) {
    u64 d; asm("mul.rn.f32x2 %0, %1, %2;" : "=l"(d) : "l"(a), "l"(b));
    return d;
}
__device__ __forceinline__ u64 pack2(float lo, float hi) {
    u64 r; asm("mov.b64 %0, {%1, %2};" : "=l"(r) : "f"(lo), "f"(hi)); return r;
}
__device__ __forceinline__ void unpack2(u64 v, float& lo, float& hi) {
    asm("mov.b64 {%0, %1}, %2;" : "=f"(lo), "=f"(hi) : "l"(v));
}

// ---------------- main persistent kernel -----------------------------------------
__global__ __launch_bounds__(128, 3)
void bilstm_kernel(const float* __restrict__ x,
                   const int* __restrict__ lengths,
                   const float* __restrict__ w_ih,
                   const float* __restrict__ w_hh,
                   const float* __restrict__ b_ih,
                   const float* __restrict__ b_hh,
                   const float* __restrict__ fc_w,
                   const float* __restrict__ fc_b,
                   const float* __restrict__ fc2_w,
                   const float* __restrict__ fc2_b,
                   float* __restrict__ out)
{
    const int lane = threadIdx.x & 31;
    const int wrp  = threadIdx.x >> 5;

    __shared__ __align__(16) float hsh[2][4][32];   // per-warp h broadcast (dbl buf)
    __shared__ __align__(16) float xs[4][2][32];    // per-warp x chunk ring (dbl buf)

    // Fold the sigmoid/tanh argument scales into all gate weights:
    //   sigmoid(v) = rcp(1 + ex2(-1.4427 v)),  tanh(v) = 2 rcp(1 + ex2(-2.8854 v)) - 1
    const float gsc[4] = {-1.44269504f, -1.44269504f, -2.88539008f, -1.44269504f};

    u64 whh[4][16];
    u64 wib[4];                       // (sc * w_ih_row, sc * (b_ih + b_hh))
#pragma unroll
    for (int g = 0; g < 4; ++g) {
        const int row = g * 32 + lane;
        const float sc = gsc[g];
        wib[g] = pack2(sc * __ldg(w_ih + row),
                       sc * (__ldg(b_ih + row) + __ldg(b_hh + row)));
#pragma unroll
        for (int p = 0; p < 16; ++p) {
            float2 wv = *reinterpret_cast<const float2*>(w_hh + row * 32 + 2 * p);
            whh[g][p] = pack2(sc * wv.x, sc * wv.y);
        }
    }

    const unsigned FULL = 0xffffffffu;

    float h, cc;

    // One LSTM step. No branches, no gmem. cb: x chunk buffer, i: index in chunk,
    // bufIdx: h broadcast buffer.
    auto lstm_step = [&](int cb, int i, int bufIdx) {
        hsh[bufIdx][wrp][lane] = h;
        __syncwarp();

        const ulonglong2* hp =
            reinterpret_cast<const ulonglong2*>(&hsh[bufIdx][wrp][0]);

        ulonglong2 hv = hp[0];                     // LDS.128 broadcast
        u64 a0 = mul2(hv.x, whh[0][0]);
        u64 a1 = mul2(hv.x, whh[1][0]);
        u64 a2 = mul2(hv.x, whh[2][0]);
        u64 a3 = mul2(hv.x, whh[3][0]);
        a0 = ffma2(hv.y, whh[0][1], a0);
        a1 = ffma2(hv.y, whh[1][1], a1);
        a2 = ffma2(hv.y, whh[2][1], a2);
        a3 = ffma2(hv.y, whh[3][1], a3);
#pragma unroll
        for (int q = 1; q < 8; ++q) {
            hv = hp[q];
            a0 = ffma2(hv.x, whh[0][2 * q], a0);
            a1 = ffma2(hv.x, whh[1][2 * q], a1);
            a2 = ffma2(hv.x, whh[2][2 * q], a2);
            a3 = ffma2(hv.x, whh[3][2 * q], a3);
            a0 = ffma2(hv.y, whh[0][2 * q + 1], a0);
            a1 = ffma2(hv.y, whh[1][2 * q + 1], a1);
            a2 = ffma2(hv.y, whh[2][2 * q + 1], a2);
            a3 = ffma2(hv.y, whh[3][2 * q + 1], a3);
        }

        // x + bias enter last so their LDS overlaps the matvec chain:
        // (lo += x * sc*w_ih, hi += 1 * sc*bias)
        const u64 xt2 = pack2(xs[wrp][cb][i], 1.0f);
        a0 = ffma2(xt2, wib[0], a0);
        a1 = ffma2(xt2, wib[1], a1);
        a2 = ffma2(xt2, wib[2], a2);
        a3 = ffma2(xt2, wib[3], a3);

        float lo, hi;
        unpack2(a0, lo, hi); const float gi = lo + hi;   // pre-scaled args
        unpack2(a1, lo, hi); const float gf = lo + hi;
        unpack2(a2, lo, hi); const float gg = lo + hi;
        unpack2(a3, lo, hi); const float go = lo + hi;

        const float iv = fast_rcp(1.0f + fast_ex2(gi));
        const float fv = fast_rcp(1.0f + fast_ex2(gf));
        const float gv = fmaf(2.0f, fast_rcp(1.0f + fast_ex2(gg)), -1.0f);
        const float ov = fast_rcp(1.0f + fast_ex2(go));

        cc = fmaf(fv, cc, iv * gv);
        const float tv = fmaf(2.0f,
            fast_rcp(1.0f + fast_ex2(-2.88539008f * cc)), -1.0f);
        h = ov * tv;
    };

    for (;;) {
        int s0 = 0;
        if (lane == 0) s0 = atomicAdd(&g_counter, 1);
        s0 = __shfl_sync(FULL, s0, 0);
        if (s0 >= B_SZ) break;

        const int idx = g_order[s0];
        const int len = __ldg(lengths + idx);
        const float* xb = x + (size_t)idx * T_SZ;

        h = 0.0f; cc = 0.0f;

        int t = len - 1;
        const int c0 = t >> 5;
        // stage the first (possibly partial) chunk; prefetch the next
        xs[wrp][c0 & 1][lane] = __ldg(xb + (c0 << 5) + lane);
        float pend = (c0 > 0) ? __ldg(xb + ((c0 - 1) << 5) + lane) : 0.0f;

        int buf = 0;

        // peel: partial first chunk
#pragma unroll 2
        for (int i = t & 31; i >= 0; --i) {
            lstm_step(c0 & 1, i, buf);
            buf ^= 1;
        }

        // full chunks: branch-free unrolled steps; 1 STS + 1 LDG per 32 steps
#pragma unroll 1
        for (int c = c0 - 1; c >= 0; --c) {
            xs[wrp][c & 1][lane] = pend;            // visible after step's syncwarp
            pend = (c > 0) ? __ldg(xb + ((c - 1) << 5) + lane) : 0.0f;
#pragma unroll 4
            for (int i = 31; i >= 0; --i) {
                lstm_step(c & 1, i, buf);
                buf ^= 1;
            }
        }

        // ---- FC head: sigmoid(fc2(elu(fc1(h)))) ----
        __syncwarp();
        hsh[0][wrp][lane] = h;
        __syncwarp();

        float o1 = __ldg(fc_b + lane);
        float o2 = __ldg(fc_b + lane + 32);
#pragma unroll
        for (int k = 0; k < 32; ++k) {
            const float hk = hsh[0][wrp][k];
            o1 = fmaf(hk, __ldg(fc_w + lane * 32 + k), o1);
            o2 = fmaf(hk, __ldg(fc_w + (lane + 32) * 32 + k), o2);
        }
        o1 = (o1 > 0.0f) ? o1 : (fast_ex2(1.44269504f * o1) - 1.0f);  // ELU
        o2 = (o2 > 0.0f) ? o2 : (fast_ex2(1.44269504f * o2) - 1.0f);

        float part = o1 * __ldg(fc2_w + lane) + o2 * __ldg(fc2_w + lane + 32);
#pragma unroll
        for (int d = 16; d >= 1; d >>= 1)
            part += __shfl_xor_sync(FULL, part, d);

        if (lane == 0)
            out[idx] = sigmoid_(part + __ldg(fc2_b));

        __syncwarp();
    }
}

extern "C" void kernel_launch(void* const* d_in, const int* in_sizes, int n_in,
                              void* d_out, int out_size)
{
    const float* x       = (const float*)d_in[0];
    const int*   lengths = (const int*)  d_in[1];
    const float* w_ih    = (const float*)d_in[2];
    const float* w_hh    = (const float*)d_in[3];
    const float* b_ih    = (const float*)d_in[4];
    const float* b_hh    = (const float*)d_in[5];
    const float* fc_w    = (const float*)d_in[6];
    const float* fc_b    = (const float*)d_in[7];
    const float* fc2_w   = (const float*)d_in[8];
    const float* fc2_b   = (const float*)d_in[9];
    float* out = (float*)d_out;

    sort_kernel<<<1, 1024>>>(lengths);
    bilstm_kernel<<<444, 128>>>(x, lengths, w_ih, w_hh, b_ih, b_hh,
                                fc_w, fc_b, fc2_w, fc2_b, out);
}